// round 10
// baseline (speedup 1.0000x reference)
#include <cuda_runtime.h>
#include <math.h>

#define BB 256
#define NN 2048
#define RR 64
#define DD 64
#define TT 8
#define HH 128
#define KD 128

#define GRID    256
#define NTHR    256
#define MCH     32            // nodes per chunk
#define MS      (MCH + 4)     // smem row stride
#define LMAX    256
#define NGRP    (LMAX * TT)   // bucket key = t*LMAX + L

// ---------------- global scratch (static: no allocation) ----------------
__device__ unsigned           g_arrive;
__device__ volatile unsigned  g_release;
__device__ int                g_cnt[NGRP];
__device__ int                g_cur[NGRP];             // scatter cursors
__device__ int                g_off[NGRP + 1];
__device__ int                g_ccum[TT * (LMAX + 1)]; // per-type chunk prefix over levels
__device__ int                g_tcur[TT];              // per-type team chunk cursor
__device__ int                g_maxl;
__device__ unsigned long long g_items[BB * (NN - RR)]; // (b<<33)|(n<<22)|(p0<<11)|p1
__device__ unsigned           g_flag[BB * NN];         // node-done flags

__global__ void reset_kernel()
{
    int gt = blockIdx.x * NTHR + threadIdx.x;
    for (int i = gt; i < BB * NN; i += GRID * NTHR) g_flag[i] = 0u;
    for (int i = gt; i < NGRP;   i += GRID * NTHR) g_cnt[i] = 0;
    if (gt < TT) g_tcur[gt] = 0;
    if (gt == 0) { g_arrive = 0; g_release = 0; g_maxl = 0; }
}

__device__ __forceinline__ void grid_barrier(int k)
{
    __syncthreads();
    if (threadIdx.x == 0) {
        __threadfence();   // release side
        unsigned old = atomicAdd(&g_arrive, 1u);
        if (old == (unsigned)(k * GRID - 1)) {
            g_release = (unsigned)k;
        } else {
            while (g_release < (unsigned)k) { }
        }
        __threadfence();   // acquire side
    }
    __syncthreads();
}

// STRONG scoped flag ops (weak .cg ops never pair with fences).
__device__ __forceinline__ unsigned ld_acq_u32(const unsigned* p)
{
    unsigned v;
    asm volatile("ld.acquire.gpu.global.u32 %0, [%1];"
                 : "=r"(v) : "l"(p) : "memory");
    return v;
}
__device__ __forceinline__ void st_rel_u32(unsigned* p, unsigned v)
{
    asm volatile("st.release.gpu.global.u32 [%0], %1;"
                 :: "l"(p), "r"(v) : "memory");
}

__global__ __launch_bounds__(NTHR, 2)
void dag_global_kernel(const float* __restrict__ roots,
                       const float* __restrict__ W1,
                       const float* __restrict__ b1,
                       const float* __restrict__ W2,
                       const float* __restrict__ b2,
                       const int*   __restrict__ g_idx,
                       const int*   __restrict__ g_typ,
                       float*       __restrict__ buf)
{
    const int b    = blockIdx.x;
    const int tid  = threadIdx.x;
    const int lane = tid & 31;
    const int wid  = tid >> 5;

    __shared__ __align__(16) float s_xs[KD * MS];
    __shared__ __align__(16) float s_hs[HH * MS];
    __shared__ int s_ccum[LMAX + 1];
    __shared__ int s_k;

    unsigned short* s_lvl  = (unsigned short*)s_xs;   // prep aliases
    unsigned short* s_pidx = (unsigned short*)s_hs;

    const int* idxb = g_idx + (size_t)b * (NN * 2);
    const int* typb = g_typ + (size_t)b * NN;

    // ---------------- prep ----------------
    {
        const float* rs = roots + (size_t)b * (RR * DD);
        float*       bb = buf   + (size_t)b * (NN * DD);
        for (int i = tid; i < RR * DD; i += NTHR) bb[i] = rs[i];
        for (int k = tid; k < NN * 2; k += NTHR)
            s_pidx[k] = (unsigned short)idxb[k];
        // root flags (made globally visible by grid_barrier(3)'s fences)
        for (int n = tid; n < RR; n += NTHR)
            g_flag[b * NN + n] = 1u;
    }
    __syncthreads();

    if (tid == 0) {
        for (int n = 0; n < RR; ++n) s_lvl[n] = 0;
        int mx = 0;
        for (int n = RR; n < NN; ++n) {
            int l0 = s_lvl[s_pidx[n * 2 + 0]];
            int l1 = s_lvl[s_pidx[n * 2 + 1]];
            int l  = 1 + (l0 > l1 ? l0 : l1);
            s_lvl[n] = (unsigned short)l;
            if (l > mx) mx = l;
        }
        atomicMax(&g_maxl, mx);
    }
    __syncthreads();

    for (int n = RR + tid; n < NN; n += NTHR)
        atomicAdd(&g_cnt[typb[n] * LMAX + (int)s_lvl[n]], 1);

    grid_barrier(1);

    // CTA0: per-type prefix sums (8 threads, one per type)
    if (b == 0) {
        __shared__ int s_ttot[TT];
        if (tid < TT) {
            int tot = 0;
            for (int L = 0; L < LMAX; ++L) tot += g_cnt[tid * LMAX + L];
            s_ttot[tid] = tot;
        }
        __syncthreads();
        if (tid < TT) {
            int base = 0;
            for (int t = 0; t < tid; ++t) base += s_ttot[t];
            int acc = base;
            for (int L = 0; L < LMAX; ++L) {
                g_off[tid * LMAX + L] = acc;
                g_cur[tid * LMAX + L] = acc;
                acc += g_cnt[tid * LMAX + L];
            }
            if (tid == TT - 1) g_off[NGRP] = acc;
            int cacc = 0;
            g_ccum[tid * (LMAX + 1)] = 0;
            for (int L = 1; L <= LMAX; ++L) {
                cacc += (g_cnt[tid * LMAX + L] + MCH - 1) / MCH;
                g_ccum[tid * (LMAX + 1) + L] = cacc;
            }
        }
    }
    grid_barrier(2);

    // scatter items (64-bit packed with parent indices)
    for (int n = RR + tid; n < NN; n += NTHR) {
        int key = typb[n] * LMAX + (int)s_lvl[n];
        int pos = atomicAdd(&g_cur[key], 1);
        unsigned long long p0 = s_pidx[n * 2 + 0];
        unsigned long long p1 = s_pidx[n * 2 + 1];
        g_items[pos] = ((unsigned long long)b << 33)
                     | ((unsigned long long)n << 22) | (p0 << 11) | p1;
    }
    grid_barrier(3);

    // ---------------- dataflow main loop ----------------
    // Type affinity chosen so CO-RESIDENT CTAs share a type: classic placement
    // maps smid = LUT[bid % 148], so CTAs b and b+148 land on the same SM.
    // (b % 148) % TT gives them identical types -> one shared 96 KB weight
    // working set per SM -> L1-resident (L1D ~152 KB after smem carveout).
    const int tmy = (b % 148) % TT;
    const int Lmx = *(volatile int*)&g_maxl;

    for (int i = tid; i <= LMAX; i += NTHR) s_ccum[i] = g_ccum[tmy * (LMAX + 1) + i];
    __syncthreads();
    const int total = s_ccum[Lmx];

    const float* w1t = W1 + (size_t)tmy * (KD * HH);
    const float* w2t = W2 + (size_t)tmy * (HH * DD);
    const float  bv1 = __ldg(b1 + tmy * HH + (tid & 127));
    const float  bv2 = __ldg(b2 + tmy * DD + (tid & 63));

    const int j128 = tid & 127, mh = tid >> 7;
    const int d64  = tid & 63,  mq = tid >> 6;

    while (true) {
        if (tid == 0) s_k = atomicAdd(&g_tcur[tmy], 1);
        __syncthreads();
        const int k = s_k;
        if (k >= total) break;

        // locate (level, chunk-in-level)
        int loL = 1, hiL = Lmx;
        while (loL < hiL) { int mid = (loL + hiL) >> 1;
                            if (s_ccum[mid] > k) hiL = mid; else loL = mid + 1; }
        const int L    = loL;
        const int cidx = k - s_ccum[L - 1];
        const int base = g_off[tmy * LMAX + L];
        const int cnt  = g_off[tmy * LMAX + L + 1] - base;
        const int goff = base + cidx * MCH;
        const int Mc   = min(MCH, cnt - cidx * MCH);

        // ---- poll parents ready (strong acquire loads) ----
        unsigned long long itv[4];
        #pragma unroll
        for (int r = 0; r < 4; ++r) {
            int m = wid + r * 8;
            itv[r] = 0;
            if (m < Mc) {
                itv[r] = g_items[goff + m];
                unsigned gb = (unsigned)(itv[r] >> 33);
                unsigned p0 = (unsigned)(itv[r] >> 11) & 2047u;
                unsigned p1 = (unsigned)itv[r] & 2047u;
                const unsigned* f0 = &g_flag[gb * NN + p0];
                const unsigned* f1 = &g_flag[gb * NN + p1];
                while (ld_acq_u32(f0) == 0u) { }
                while (ld_acq_u32(f1) == 0u) { }
            }
        }
        __threadfence();   // belt-and-suspenders acquire

        // ---- gather ----
        #pragma unroll
        for (int r = 0; r < 4; ++r) {
            int m = wid + r * 8;
            if (m < Mc) {
                unsigned gb = (unsigned)(itv[r] >> 33);
                unsigned p0 = (unsigned)(itv[r] >> 11) & 2047u;
                unsigned p1 = (unsigned)itv[r] & 2047u;
                const float* r0 = buf + ((size_t)gb * NN + p0) * DD;
                const float* r1 = buf + ((size_t)gb * NN + p1) * DD;
                s_xs[(lane      ) * MS + m] = __ldcg(r0 + lane);
                s_xs[(lane + 32 ) * MS + m] = __ldcg(r0 + lane + 32);
                s_xs[(lane + 64 ) * MS + m] = __ldcg(r1 + lane);
                s_xs[(lane + 96 ) * MS + m] = __ldcg(r1 + lane + 32);
            }
        }
        __syncthreads();

        // ---- GEMM1 + bias + GELU ----
        {
            const float* wp = w1t + j128;
            const float* xp = s_xs + mh * 16;
            float a[16];
            #pragma unroll
            for (int q = 0; q < 16; ++q) a[q] = 0.f;
            #pragma unroll 2
            for (int i = 0; i < KD; ++i) {
                float wv = __ldg(wp + i * HH);
                float4 x0 = *(const float4*)(xp + i * MS     );
                float4 x1 = *(const float4*)(xp + i * MS + 4 );
                float4 x2 = *(const float4*)(xp + i * MS + 8 );
                float4 x3 = *(const float4*)(xp + i * MS + 12);
                a[0]  += x0.x * wv;  a[1]  += x0.y * wv;
                a[2]  += x0.z * wv;  a[3]  += x0.w * wv;
                a[4]  += x1.x * wv;  a[5]  += x1.y * wv;
                a[6]  += x1.z * wv;  a[7]  += x1.w * wv;
                a[8]  += x2.x * wv;  a[9]  += x2.y * wv;
                a[10] += x2.z * wv;  a[11] += x2.w * wv;
                a[12] += x3.x * wv;  a[13] += x3.y * wv;
                a[14] += x3.z * wv;  a[15] += x3.w * wv;
            }
            #pragma unroll
            for (int q = 0; q < 16; ++q) {
                float v = a[q] + bv1;
                a[q] = 0.5f * v * (1.0f + erff(v * 0.70710678118654752440f));
            }
            float* hp = s_hs + j128 * MS + mh * 16;
            *(float4*)(hp     ) = make_float4(a[0],  a[1],  a[2],  a[3]);
            *(float4*)(hp + 4 ) = make_float4(a[4],  a[5],  a[6],  a[7]);
            *(float4*)(hp + 8 ) = make_float4(a[8],  a[9],  a[10], a[11]);
            *(float4*)(hp + 12) = make_float4(a[12], a[13], a[14], a[15]);
        }
        __syncthreads();

        // ---- GEMM2 + bias + store ----
        {
            const float* wp = w2t + d64;
            const float* hp = s_hs + mq * 8;
            float a0=0.f,a1=0.f,a2=0.f,a3=0.f,a4=0.f,a5=0.f,a6=0.f,a7=0.f;
            #pragma unroll 4
            for (int j = 0; j < HH; ++j) {
                float wv = __ldg(wp + j * DD);
                float4 h0 = *(const float4*)(hp + j * MS    );
                float4 h1 = *(const float4*)(hp + j * MS + 4);
                a0 += h0.x * wv;  a1 += h0.y * wv;
                a2 += h0.z * wv;  a3 += h0.w * wv;
                a4 += h1.x * wv;  a5 += h1.y * wv;
                a6 += h1.z * wv;  a7 += h1.w * wv;
            }
            float o[8] = {a0,a1,a2,a3,a4,a5,a6,a7};
            #pragma unroll
            for (int q = 0; q < 8; ++q) {
                int m = mq * 8 + q;
                if (m < Mc) {
                    unsigned long long it = g_items[goff + m];
                    unsigned gb = (unsigned)(it >> 33);
                    unsigned gn = (unsigned)(it >> 22) & 2047u;
                    buf[((size_t)gb * NN + gn) * DD + d64] = o[q] + bv2;
                }
            }
        }

        // ---- publish: bar (folds all CTA stores into HB) -> fence -> release-store
        __syncthreads();
        __threadfence();
        if (tid < Mc) {
            unsigned long long it = g_items[goff + tid];
            unsigned gb = (unsigned)(it >> 33);
            unsigned gn = (unsigned)(it >> 22) & 2047u;
            st_rel_u32(&g_flag[gb * NN + gn], 1u);
        }
        __syncthreads();    // protect s_xs/s_hs/s_k reuse
    }
}

extern "C" void kernel_launch(void* const* d_in, const int* in_sizes, int n_in,
                              void* d_out, int out_size)
{
    const float* roots = (const float*)d_in[0];
    const float* W1    = (const float*)d_in[1];
    const float* b1    = (const float*)d_in[2];
    const float* W2    = (const float*)d_in[3];
    const float* b2    = (const float*)d_in[4];
    const int*   idx   = (const int*)  d_in[5];
    const int*   typ   = (const int*)  d_in[6];
    float*       out   = (float*)d_out;

    reset_kernel<<<GRID, NTHR>>>();
    dag_global_kernel<<<GRID, NTHR>>>(roots, W1, b1, W2, b2, idx, typ, out);
}

// round 11
// speedup vs baseline: 1.3245x; 1.3245x over previous
#include <cuda_runtime.h>
#include <math.h>

#define BB 256
#define NN 2048
#define RR 64
#define DD 64
#define TT 8
#define HH 128
#define KD 128

#define GRID    296           // 2 CTAs on every SM (148 x 2), all co-resident
#define NTHR    256
#define MCH     32            // nodes per chunk
#define MS      (MCH + 4)     // smem row stride
#define LMAX    256
#define NGRP    (LMAX * TT)   // bucket key = t*LMAX + L

// ---------------- global scratch (static: no allocation) ----------------
__device__ unsigned           g_arrive;
__device__ volatile unsigned  g_release;
__device__ int                g_cnt[NGRP];
__device__ int                g_cur[NGRP];             // scatter cursors
__device__ int                g_off[NGRP + 1];
__device__ int                g_ccum[TT * (LMAX + 1)]; // per-type chunk prefix over levels
__device__ int                g_tcur[TT];              // per-type team chunk cursor
__device__ int                g_maxl;
__device__ unsigned long long g_items[BB * (NN - RR)]; // (b<<33)|(n<<22)|(p0<<11)|p1
__device__ unsigned           g_flag[BB * NN];         // node-done flags

__global__ void reset_kernel()
{
    int gt = blockIdx.x * NTHR + threadIdx.x;
    for (int i = gt; i < BB * NN; i += GRID * NTHR) g_flag[i] = 0u;
    for (int i = gt; i < NGRP;   i += GRID * NTHR) g_cnt[i] = 0;
    if (gt < TT) g_tcur[gt] = 0;
    if (gt == 0) { g_arrive = 0; g_release = 0; g_maxl = 0; }
}

__device__ __forceinline__ void grid_barrier(int k)
{
    __syncthreads();
    if (threadIdx.x == 0) {
        __threadfence();   // release side
        unsigned old = atomicAdd(&g_arrive, 1u);
        if (old == (unsigned)(k * GRID - 1)) {
            g_release = (unsigned)k;
        } else {
            while (g_release < (unsigned)k) { }
        }
        __threadfence();   // acquire side
    }
    __syncthreads();
}

// STRONG scoped flag ops — the canonical PTX release/acquire message pair.
__device__ __forceinline__ unsigned ld_acq_u32(const unsigned* p)
{
    unsigned v;
    asm volatile("ld.acquire.gpu.global.u32 %0, [%1];"
                 : "=r"(v) : "l"(p) : "memory");
    return v;
}
__device__ __forceinline__ void st_rel_u32(unsigned* p, unsigned v)
{
    asm volatile("st.release.gpu.global.u32 [%0], %1;"
                 :: "l"(p), "r"(v) : "memory");
}

__global__ __launch_bounds__(NTHR, 2)
void dag_global_kernel(const float* __restrict__ roots,
                       const float* __restrict__ W1,
                       const float* __restrict__ b1,
                       const float* __restrict__ W2,
                       const float* __restrict__ b2,
                       const int*   __restrict__ g_idx,
                       const int*   __restrict__ g_typ,
                       float*       __restrict__ buf)
{
    const int b    = blockIdx.x;
    const int tid  = threadIdx.x;
    const int lane = tid & 31;
    const int wid  = tid >> 5;

    __shared__ __align__(16) float s_xs[KD * MS];
    __shared__ __align__(16) float s_hs[HH * MS];
    __shared__ unsigned long long s_it[MCH];     // chunk items (smem copy)
    __shared__ int s_ccum[LMAX + 1];
    __shared__ int s_k;

    unsigned short* s_lvl  = (unsigned short*)s_xs;   // prep aliases
    unsigned short* s_pidx = (unsigned short*)s_hs;

    // ---------------- prep (graphs 0..BB-1 handled by CTAs 0..BB-1) ----------
    if (b < BB) {
        const int* idxb = g_idx + (size_t)b * (NN * 2);
        const float* rs = roots + (size_t)b * (RR * DD);
        float*       bb = buf   + (size_t)b * (NN * DD);
        for (int i = tid; i < RR * DD; i += NTHR) bb[i] = rs[i];
        for (int k = tid; k < NN * 2; k += NTHR)
            s_pidx[k] = (unsigned short)idxb[k];
        for (int n = tid; n < RR; n += NTHR)
            g_flag[b * NN + n] = 1u;
        __syncthreads();

        if (tid == 0) {
            for (int n = 0; n < RR; ++n) s_lvl[n] = 0;
            int mx = 0;
            for (int n = RR; n < NN; ++n) {
                int l0 = s_lvl[s_pidx[n * 2 + 0]];
                int l1 = s_lvl[s_pidx[n * 2 + 1]];
                int l  = 1 + (l0 > l1 ? l0 : l1);
                s_lvl[n] = (unsigned short)l;
                if (l > mx) mx = l;
            }
            atomicMax(&g_maxl, mx);
        }
        __syncthreads();

        const int* typb = g_typ + (size_t)b * NN;
        for (int n = RR + tid; n < NN; n += NTHR)
            atomicAdd(&g_cnt[typb[n] * LMAX + (int)s_lvl[n]], 1);
    }

    grid_barrier(1);

    // CTA0: per-type prefix sums (8 threads, one per type)
    if (b == 0) {
        __shared__ int s_ttot[TT];
        if (tid < TT) {
            int tot = 0;
            for (int L = 0; L < LMAX; ++L) tot += g_cnt[tid * LMAX + L];
            s_ttot[tid] = tot;
        }
        __syncthreads();
        if (tid < TT) {
            int base = 0;
            for (int t = 0; t < tid; ++t) base += s_ttot[t];
            int acc = base;
            for (int L = 0; L < LMAX; ++L) {
                g_off[tid * LMAX + L] = acc;
                g_cur[tid * LMAX + L] = acc;
                acc += g_cnt[tid * LMAX + L];
            }
            if (tid == TT - 1) g_off[NGRP] = acc;
            int cacc = 0;
            g_ccum[tid * (LMAX + 1)] = 0;
            for (int L = 1; L <= LMAX; ++L) {
                cacc += (g_cnt[tid * LMAX + L] + MCH - 1) / MCH;
                g_ccum[tid * (LMAX + 1) + L] = cacc;
            }
        }
    }
    grid_barrier(2);

    // scatter items (64-bit packed with parent indices)
    if (b < BB) {
        const int* typb = g_typ + (size_t)b * NN;
        for (int n = RR + tid; n < NN; n += NTHR) {
            int key = typb[n] * LMAX + (int)s_lvl[n];
            int pos = atomicAdd(&g_cur[key], 1);
            unsigned long long p0 = s_pidx[n * 2 + 0];
            unsigned long long p1 = s_pidx[n * 2 + 1];
            g_items[pos] = ((unsigned long long)b << 33)
                         | ((unsigned long long)n << 22) | (p0 << 11) | p1;
        }
    }
    grid_barrier(3);

    // ---------------- dataflow main loop ----------------
    const int tmy = b % TT;              // uniform teams of 37 CTAs
    const int Lmx = *(volatile int*)&g_maxl;

    for (int i = tid; i <= LMAX; i += NTHR) s_ccum[i] = g_ccum[tmy * (LMAX + 1) + i];
    __syncthreads();
    const int total = s_ccum[Lmx];

    const float* w1t = W1 + (size_t)tmy * (KD * HH);
    const float* w2t = W2 + (size_t)tmy * (HH * DD);
    const float  bv1 = __ldg(b1 + tmy * HH + (tid & 127));
    const float  bv2 = __ldg(b2 + tmy * DD + (tid & 63));

    const int j128 = tid & 127, mh = tid >> 7;
    const int d64  = tid & 63,  mq = tid >> 6;

    while (true) {
        if (tid == 0) s_k = atomicAdd(&g_tcur[tmy], 1);
        __syncthreads();
        const int k = s_k;
        if (k >= total) break;

        // locate (level, chunk-in-level)
        int loL = 1, hiL = Lmx;
        while (loL < hiL) { int mid = (loL + hiL) >> 1;
                            if (s_ccum[mid] > k) hiL = mid; else loL = mid + 1; }
        const int L    = loL;
        const int cidx = k - s_ccum[L - 1];
        const int base = g_off[tmy * LMAX + L];
        const int cnt  = g_off[tmy * LMAX + L + 1] - base;
        const int goff = base + cidx * MCH;
        const int Mc   = min(MCH, cnt - cidx * MCH);

        // stage items into smem (consumed after the gather sync)
        if (tid < Mc) s_it[tid] = g_items[goff + tid];

        // ---- poll parents ready (strong acquire loads; warp-broadcast) ----
        unsigned long long itv[4];
        #pragma unroll
        for (int r = 0; r < 4; ++r) {
            int m = wid + r * 8;
            itv[r] = 0;
            if (m < Mc) {
                itv[r] = g_items[goff + m];
                unsigned gb = (unsigned)(itv[r] >> 33);
                unsigned p0 = (unsigned)(itv[r] >> 11) & 2047u;
                unsigned p1 = (unsigned)itv[r] & 2047u;
                const unsigned* f0 = &g_flag[gb * NN + p0];
                const unsigned* f1 = &g_flag[gb * NN + p1];
                while (ld_acq_u32(f0) == 0u) { }
                while (ld_acq_u32(f1) == 0u) { }
            }
        }

        // ---- gather (ordered after acquire loads in program order) ----
        #pragma unroll
        for (int r = 0; r < 4; ++r) {
            int m = wid + r * 8;
            if (m < Mc) {
                unsigned gb = (unsigned)(itv[r] >> 33);
                unsigned p0 = (unsigned)(itv[r] >> 11) & 2047u;
                unsigned p1 = (unsigned)itv[r] & 2047u;
                const float* r0 = buf + ((size_t)gb * NN + p0) * DD;
                const float* r1 = buf + ((size_t)gb * NN + p1) * DD;
                s_xs[(lane      ) * MS + m] = __ldcg(r0 + lane);
                s_xs[(lane + 32 ) * MS + m] = __ldcg(r0 + lane + 32);
                s_xs[(lane + 64 ) * MS + m] = __ldcg(r1 + lane);
                s_xs[(lane + 96 ) * MS + m] = __ldcg(r1 + lane + 32);
            }
        }
        __syncthreads();

        // ---- GEMM1 + bias + GELU: MLP-4 weight prefetch ----
        {
            const float* wp = w1t + j128;
            const float* xp = s_xs + mh * 16;
            float a[16];
            #pragma unroll
            for (int q = 0; q < 16; ++q) a[q] = 0.f;
            #pragma unroll 1
            for (int i = 0; i < KD; i += 4) {
                float w0 = __ldg(wp + (i + 0) * HH);
                float w1v = __ldg(wp + (i + 1) * HH);
                float w2v = __ldg(wp + (i + 2) * HH);
                float w3v = __ldg(wp + (i + 3) * HH);
                #pragma unroll
                for (int u = 0; u < 4; ++u) {
                    float wv = (u == 0) ? w0 : (u == 1) ? w1v : (u == 2) ? w2v : w3v;
                    const float* xr = xp + (i + u) * MS;
                    float4 x0 = *(const float4*)(xr     );
                    float4 x1 = *(const float4*)(xr + 4 );
                    float4 x2 = *(const float4*)(xr + 8 );
                    float4 x3 = *(const float4*)(xr + 12);
                    a[0]  += x0.x * wv;  a[1]  += x0.y * wv;
                    a[2]  += x0.z * wv;  a[3]  += x0.w * wv;
                    a[4]  += x1.x * wv;  a[5]  += x1.y * wv;
                    a[6]  += x1.z * wv;  a[7]  += x1.w * wv;
                    a[8]  += x2.x * wv;  a[9]  += x2.y * wv;
                    a[10] += x2.z * wv;  a[11] += x2.w * wv;
                    a[12] += x3.x * wv;  a[13] += x3.y * wv;
                    a[14] += x3.z * wv;  a[15] += x3.w * wv;
                }
            }
            #pragma unroll
            for (int q = 0; q < 16; ++q) {
                float v = a[q] + bv1;
                a[q] = 0.5f * v * (1.0f + erff(v * 0.70710678118654752440f));
            }
            float* hp = s_hs + j128 * MS + mh * 16;
            *(float4*)(hp     ) = make_float4(a[0],  a[1],  a[2],  a[3]);
            *(float4*)(hp + 4 ) = make_float4(a[4],  a[5],  a[6],  a[7]);
            *(float4*)(hp + 8 ) = make_float4(a[8],  a[9],  a[10], a[11]);
            *(float4*)(hp + 12) = make_float4(a[12], a[13], a[14], a[15]);
        }
        __syncthreads();

        // ---- GEMM2 + bias + store: MLP-4 weight prefetch ----
        {
            const float* wp = w2t + d64;
            const float* hp = s_hs + mq * 8;
            float a0=0.f,a1=0.f,a2=0.f,a3=0.f,a4=0.f,a5=0.f,a6=0.f,a7=0.f;
            #pragma unroll 1
            for (int j = 0; j < HH; j += 4) {
                float w0 = __ldg(wp + (j + 0) * DD);
                float w1v = __ldg(wp + (j + 1) * DD);
                float w2v = __ldg(wp + (j + 2) * DD);
                float w3v = __ldg(wp + (j + 3) * DD);
                #pragma unroll
                for (int u = 0; u < 4; ++u) {
                    float wv = (u == 0) ? w0 : (u == 1) ? w1v : (u == 2) ? w2v : w3v;
                    const float* hr = hp + (j + u) * MS;
                    float4 h0 = *(const float4*)(hr    );
                    float4 h1 = *(const float4*)(hr + 4);
                    a0 += h0.x * wv;  a1 += h0.y * wv;
                    a2 += h0.z * wv;  a3 += h0.w * wv;
                    a4 += h1.x * wv;  a5 += h1.y * wv;
                    a6 += h1.z * wv;  a7 += h1.w * wv;
                }
            }
            float o[8] = {a0,a1,a2,a3,a4,a5,a6,a7};
            #pragma unroll
            for (int q = 0; q < 8; ++q) {
                int m = mq * 8 + q;
                if (m < Mc) {
                    unsigned long long it = s_it[m];             // broadcast LDS
                    unsigned gb = (unsigned)(it >> 33);
                    unsigned gn = (unsigned)(it >> 22) & 2047u;
                    buf[((size_t)gb * NN + gn) * DD + d64] = o[q] + bv2;
                }
            }
        }

        // ---- publish: bar (intra-CTA HB) -> release-store (gpu-scope) ----
        __syncthreads();
        if (tid < Mc) {
            unsigned long long it = s_it[tid];
            unsigned gb = (unsigned)(it >> 33);
            unsigned gn = (unsigned)(it >> 22) & 2047u;
            st_rel_u32(&g_flag[gb * NN + gn], 1u);
        }
        __syncthreads();    // protect s_xs/s_hs/s_it/s_k reuse
    }
}

extern "C" void kernel_launch(void* const* d_in, const int* in_sizes, int n_in,
                              void* d_out, int out_size)
{
    const float* roots = (const float*)d_in[0];
    const float* W1    = (const float*)d_in[1];
    const float* b1    = (const float*)d_in[2];
    const float* W2    = (const float*)d_in[3];
    const float* b2    = (const float*)d_in[4];
    const int*   idx   = (const int*)  d_in[5];
    const int*   typ   = (const int*)  d_in[6];
    float*       out   = (float*)d_out;

    reset_kernel<<<GRID, NTHR>>>();
    dag_global_kernel<<<GRID, NTHR>>>(roots, W1, b1, W2, b2, idx, typ, out);
}

// round 12
// speedup vs baseline: 1.4141x; 1.0676x over previous
#include <cuda_runtime.h>
#include <math.h>

#define BB 256
#define NN 2048
#define RR 64
#define DD 64
#define TT 8
#define HH 128
#define KD 128

#define GRID    296           // 2 CTAs on every SM (148 x 2), all co-resident
#define NTHR    256
#define MCH     32            // nodes per chunk
#define MS      (MCH + 4)     // smem row stride
#define LMAX    256
#define NGRP    (LMAX * TT)   // bucket key = t*LMAX + L

// ---------------- global scratch (static: no allocation) ----------------
__device__ unsigned           g_arrive;
__device__ volatile unsigned  g_release;
__device__ int                g_cnt[NGRP];
__device__ int                g_cur[NGRP];             // scatter cursors
__device__ int                g_off[NGRP + 1];
__device__ int                g_ccum[TT * (LMAX + 1)]; // per-type chunk prefix over levels
__device__ int                g_tcur[TT];              // per-type team chunk cursor
__device__ int                g_maxl;
__device__ unsigned long long g_items[BB * (NN - RR)]; // (b<<33)|(n<<22)|(p0<<11)|p1
__device__ unsigned           g_flag[BB * NN];         // node-done flags

__global__ void reset_kernel()
{
    int gt = blockIdx.x * NTHR + threadIdx.x;
    for (int i = gt; i < BB * NN; i += GRID * NTHR) g_flag[i] = 0u;
    for (int i = gt; i < NGRP;   i += GRID * NTHR) g_cnt[i] = 0;
    if (gt < TT) g_tcur[gt] = 0;
    if (gt == 0) { g_arrive = 0; g_release = 0; g_maxl = 0; }
}

__device__ __forceinline__ void grid_barrier(int k)
{
    __syncthreads();
    if (threadIdx.x == 0) {
        __threadfence();   // release side
        unsigned old = atomicAdd(&g_arrive, 1u);
        if (old == (unsigned)(k * GRID - 1)) {
            g_release = (unsigned)k;
        } else {
            while (g_release < (unsigned)k) { }
        }
        __threadfence();   // acquire side
    }
    __syncthreads();
}

// STRONG scoped flag ops — the canonical PTX release/acquire message pair.
__device__ __forceinline__ unsigned ld_acq_u32(const unsigned* p)
{
    unsigned v;
    asm volatile("ld.acquire.gpu.global.u32 %0, [%1];"
                 : "=r"(v) : "l"(p) : "memory");
    return v;
}
__device__ __forceinline__ void st_rel_u32(unsigned* p, unsigned v)
{
    asm volatile("st.release.gpu.global.u32 [%0], %1;"
                 :: "l"(p), "r"(v) : "memory");
}

__global__ __launch_bounds__(NTHR, 2)
void dag_global_kernel(const float* __restrict__ roots,
                       const float* __restrict__ W1,
                       const float* __restrict__ b1,
                       const float* __restrict__ W2,
                       const float* __restrict__ b2,
                       const int*   __restrict__ g_idx,
                       const int*   __restrict__ g_typ,
                       float*       __restrict__ buf)
{
    const int b    = blockIdx.x;
    const int tid  = threadIdx.x;
    const int lane = tid & 31;
    const int wid  = tid >> 5;

    __shared__ __align__(16) float s_xs[KD * MS];
    __shared__ __align__(16) float s_hs[HH * MS];
    __shared__ unsigned long long s_it[MCH];     // chunk items (smem copy)
    __shared__ int s_ccum[LMAX + 1];
    __shared__ int s_k;

    unsigned short* s_lvl  = (unsigned short*)s_xs;   // prep aliases
    unsigned short* s_pidx = (unsigned short*)s_hs;

    // ---------------- prep (graphs 0..BB-1 handled by CTAs 0..BB-1) ----------
    if (b < BB) {
        const int* idxb = g_idx + (size_t)b * (NN * 2);
        const float* rs = roots + (size_t)b * (RR * DD);
        float*       bb = buf   + (size_t)b * (NN * DD);
        for (int i = tid; i < RR * DD; i += NTHR) bb[i] = rs[i];
        for (int k = tid; k < NN * 2; k += NTHR)
            s_pidx[k] = (unsigned short)idxb[k];
        for (int n = tid; n < RR; n += NTHR)
            g_flag[b * NN + n] = 1u;
        __syncthreads();

        if (tid == 0) {
            for (int n = 0; n < RR; ++n) s_lvl[n] = 0;
            int mx = 0;
            for (int n = RR; n < NN; ++n) {
                int l0 = s_lvl[s_pidx[n * 2 + 0]];
                int l1 = s_lvl[s_pidx[n * 2 + 1]];
                int l  = 1 + (l0 > l1 ? l0 : l1);
                s_lvl[n] = (unsigned short)l;
                if (l > mx) mx = l;
            }
            atomicMax(&g_maxl, mx);
        }
        __syncthreads();

        const int* typb = g_typ + (size_t)b * NN;
        for (int n = RR + tid; n < NN; n += NTHR)
            atomicAdd(&g_cnt[typb[n] * LMAX + (int)s_lvl[n]], 1);
    }

    grid_barrier(1);

    // CTA0: per-type prefix sums (8 threads, one per type)
    if (b == 0) {
        __shared__ int s_ttot[TT];
        if (tid < TT) {
            int tot = 0;
            for (int L = 0; L < LMAX; ++L) tot += g_cnt[tid * LMAX + L];
            s_ttot[tid] = tot;
        }
        __syncthreads();
        if (tid < TT) {
            int base = 0;
            for (int t = 0; t < tid; ++t) base += s_ttot[t];
            int acc = base;
            for (int L = 0; L < LMAX; ++L) {
                g_off[tid * LMAX + L] = acc;
                g_cur[tid * LMAX + L] = acc;
                acc += g_cnt[tid * LMAX + L];
            }
            if (tid == TT - 1) g_off[NGRP] = acc;
            int cacc = 0;
            g_ccum[tid * (LMAX + 1)] = 0;
            for (int L = 1; L <= LMAX; ++L) {
                cacc += (g_cnt[tid * LMAX + L] + MCH - 1) / MCH;
                g_ccum[tid * (LMAX + 1) + L] = cacc;
            }
        }
    }
    grid_barrier(2);

    // scatter items (64-bit packed with parent indices)
    if (b < BB) {
        const int* typb = g_typ + (size_t)b * NN;
        for (int n = RR + tid; n < NN; n += NTHR) {
            int key = typb[n] * LMAX + (int)s_lvl[n];
            int pos = atomicAdd(&g_cur[key], 1);
            unsigned long long p0 = s_pidx[n * 2 + 0];
            unsigned long long p1 = s_pidx[n * 2 + 1];
            g_items[pos] = ((unsigned long long)b << 33)
                         | ((unsigned long long)n << 22) | (p0 << 11) | p1;
        }
    }
    grid_barrier(3);

    // ---------------- dataflow main loop ----------------
    const int tmy = b % TT;              // uniform teams of 37 CTAs
    const int Lmx = *(volatile int*)&g_maxl;

    for (int i = tid; i <= LMAX; i += NTHR) s_ccum[i] = g_ccum[tmy * (LMAX + 1) + i];
    __syncthreads();
    const int total = s_ccum[Lmx];

    const float* w1t = W1 + (size_t)tmy * (KD * HH);
    const float* w2t = W2 + (size_t)tmy * (HH * DD);
    const float  bv1 = __ldg(b1 + tmy * HH + (tid & 127));
    const float  bv2 = __ldg(b2 + tmy * DD + (tid & 63));

    const int j128 = tid & 127, mh = tid >> 7;
    const int d64  = tid & 63,  mq = tid >> 6;

    while (true) {
        if (tid == 0) s_k = atomicAdd(&g_tcur[tmy], 1);
        __syncthreads();
        const int k = s_k;
        if (k >= total) break;

        // locate (level, chunk-in-level)
        int loL = 1, hiL = Lmx;
        while (loL < hiL) { int mid = (loL + hiL) >> 1;
                            if (s_ccum[mid] > k) hiL = mid; else loL = mid + 1; }
        const int L    = loL;
        const int cidx = k - s_ccum[L - 1];
        const int base = g_off[tmy * LMAX + L];
        const int cnt  = g_off[tmy * LMAX + L + 1] - base;
        const int goff = base + cidx * MCH;
        const int Mc   = min(MCH, cnt - cidx * MCH);

        // stage items into smem (consumed after the gather sync)
        if (tid < Mc) s_it[tid] = g_items[goff + tid];

        // ---- two-phase poll: batch-issue all acquire loads (MLP=8), then
        //      spin only on the (rare) zeros ----
        unsigned long long itv[4];
        const unsigned* fp0[4];
        const unsigned* fp1[4];
        unsigned fa[4], fb[4];
        #pragma unroll
        for (int r = 0; r < 4; ++r) {
            int m = wid + r * 8;
            itv[r] = 0; fa[r] = 1u; fb[r] = 1u; fp0[r] = 0; fp1[r] = 0;
            if (m < Mc) {
                itv[r] = g_items[goff + m];
                unsigned gb = (unsigned)(itv[r] >> 33);
                unsigned p0 = (unsigned)(itv[r] >> 11) & 2047u;
                unsigned p1 = (unsigned)itv[r] & 2047u;
                fp0[r] = &g_flag[gb * NN + p0];
                fp1[r] = &g_flag[gb * NN + p1];
                fa[r] = ld_acq_u32(fp0[r]);
                fb[r] = ld_acq_u32(fp1[r]);
            }
        }
        #pragma unroll
        for (int r = 0; r < 4; ++r) {
            if (fa[r] == 0u) { while (ld_acq_u32(fp0[r]) == 0u) { } }
            if (fb[r] == 0u) { while (ld_acq_u32(fp1[r]) == 0u) { } }
        }

        // ---- gather (ordered after acquire loads in program order) ----
        #pragma unroll
        for (int r = 0; r < 4; ++r) {
            int m = wid + r * 8;
            if (m < Mc) {
                unsigned gb = (unsigned)(itv[r] >> 33);
                unsigned p0 = (unsigned)(itv[r] >> 11) & 2047u;
                unsigned p1 = (unsigned)itv[r] & 2047u;
                const float* r0 = buf + ((size_t)gb * NN + p0) * DD;
                const float* r1 = buf + ((size_t)gb * NN + p1) * DD;
                s_xs[(lane      ) * MS + m] = __ldcg(r0 + lane);
                s_xs[(lane + 32 ) * MS + m] = __ldcg(r0 + lane + 32);
                s_xs[(lane + 64 ) * MS + m] = __ldcg(r1 + lane);
                s_xs[(lane + 96 ) * MS + m] = __ldcg(r1 + lane + 32);
            }
        }
        __syncthreads();

        // ---- GEMM1 + bias + GELU: software-pipelined weight loads ----
        {
            const float* wp = w1t + j128;
            const float* xp = s_xs + mh * 16;
            float a[16];
            #pragma unroll
            for (int q = 0; q < 16; ++q) a[q] = 0.f;
            float wc0 = __ldg(wp + 0 * HH);
            float wc1 = __ldg(wp + 1 * HH);
            float wc2 = __ldg(wp + 2 * HH);
            float wc3 = __ldg(wp + 3 * HH);
            #pragma unroll 1
            for (int i = 0; i < KD; i += 4) {
                const int ip = (i + 4) & (KD - 1);   // wrap: harmless reload of block 0
                float wn0 = __ldg(wp + (ip + 0) * HH);
                float wn1 = __ldg(wp + (ip + 1) * HH);
                float wn2 = __ldg(wp + (ip + 2) * HH);
                float wn3 = __ldg(wp + (ip + 3) * HH);
                #pragma unroll
                for (int u = 0; u < 4; ++u) {
                    float wv = (u == 0) ? wc0 : (u == 1) ? wc1 : (u == 2) ? wc2 : wc3;
                    const float* xr = xp + (i + u) * MS;
                    float4 x0 = *(const float4*)(xr     );
                    float4 x1 = *(const float4*)(xr + 4 );
                    float4 x2 = *(const float4*)(xr + 8 );
                    float4 x3 = *(const float4*)(xr + 12);
                    a[0]  += x0.x * wv;  a[1]  += x0.y * wv;
                    a[2]  += x0.z * wv;  a[3]  += x0.w * wv;
                    a[4]  += x1.x * wv;  a[5]  += x1.y * wv;
                    a[6]  += x1.z * wv;  a[7]  += x1.w * wv;
                    a[8]  += x2.x * wv;  a[9]  += x2.y * wv;
                    a[10] += x2.z * wv;  a[11] += x2.w * wv;
                    a[12] += x3.x * wv;  a[13] += x3.y * wv;
                    a[14] += x3.z * wv;  a[15] += x3.w * wv;
                }
                wc0 = wn0; wc1 = wn1; wc2 = wn2; wc3 = wn3;
            }
            #pragma unroll
            for (int q = 0; q < 16; ++q) {
                float v = a[q] + bv1;
                a[q] = 0.5f * v * (1.0f + erff(v * 0.70710678118654752440f));
            }
            float* hp = s_hs + j128 * MS + mh * 16;
            *(float4*)(hp     ) = make_float4(a[0],  a[1],  a[2],  a[3]);
            *(float4*)(hp + 4 ) = make_float4(a[4],  a[5],  a[6],  a[7]);
            *(float4*)(hp + 8 ) = make_float4(a[8],  a[9],  a[10], a[11]);
            *(float4*)(hp + 12) = make_float4(a[12], a[13], a[14], a[15]);
        }
        __syncthreads();

        // ---- GEMM2 + bias + store: software-pipelined weight loads ----
        {
            const float* wp = w2t + d64;
            const float* hp = s_hs + mq * 8;
            float a0=0.f,a1=0.f,a2=0.f,a3=0.f,a4=0.f,a5=0.f,a6=0.f,a7=0.f;
            float wc0 = __ldg(wp + 0 * DD);
            float wc1 = __ldg(wp + 1 * DD);
            float wc2 = __ldg(wp + 2 * DD);
            float wc3 = __ldg(wp + 3 * DD);
            #pragma unroll 1
            for (int j = 0; j < HH; j += 4) {
                const int jp = (j + 4) & (HH - 1);
                float wn0 = __ldg(wp + (jp + 0) * DD);
                float wn1 = __ldg(wp + (jp + 1) * DD);
                float wn2 = __ldg(wp + (jp + 2) * DD);
                float wn3 = __ldg(wp + (jp + 3) * DD);
                #pragma unroll
                for (int u = 0; u < 4; ++u) {
                    float wv = (u == 0) ? wc0 : (u == 1) ? wc1 : (u == 2) ? wc2 : wc3;
                    const float* hr = hp + (j + u) * MS;
                    float4 h0 = *(const float4*)(hr    );
                    float4 h1 = *(const float4*)(hr + 4);
                    a0 += h0.x * wv;  a1 += h0.y * wv;
                    a2 += h0.z * wv;  a3 += h0.w * wv;
                    a4 += h1.x * wv;  a5 += h1.y * wv;
                    a6 += h1.z * wv;  a7 += h1.w * wv;
                }
                wc0 = wn0; wc1 = wn1; wc2 = wn2; wc3 = wn3;
            }
            float o[8] = {a0,a1,a2,a3,a4,a5,a6,a7};
            #pragma unroll
            for (int q = 0; q < 8; ++q) {
                int m = mq * 8 + q;
                if (m < Mc) {
                    unsigned long long it = s_it[m];             // broadcast LDS
                    unsigned gb = (unsigned)(it >> 33);
                    unsigned gn = (unsigned)(it >> 22) & 2047u;
                    buf[((size_t)gb * NN + gn) * DD + d64] = o[q] + bv2;
                }
            }
        }

        // ---- publish: bar (intra-CTA HB) -> release-store (gpu-scope) ----
        // This sync also orders all smem reads of this iteration before the
        // next iteration's writes (s_k/s_it/s_xs), so no trailing sync needed.
        __syncthreads();
        if (tid < Mc) {
            unsigned long long it = s_it[tid];
            unsigned gb = (unsigned)(it >> 33);
            unsigned gn = (unsigned)(it >> 22) & 2047u;
            st_rel_u32(&g_flag[gb * NN + gn], 1u);
        }
    }
}

extern "C" void kernel_launch(void* const* d_in, const int* in_sizes, int n_in,
                              void* d_out, int out_size)
{
    const float* roots = (const float*)d_in[0];
    const float* W1    = (const float*)d_in[1];
    const float* b1    = (const float*)d_in[2];
    const float* W2    = (const float*)d_in[3];
    const float* b2    = (const float*)d_in[4];
    const int*   idx   = (const int*)  d_in[5];
    const int*   typ   = (const int*)  d_in[6];
    float*       out   = (float*)d_out;

    reset_kernel<<<GRID, NTHR>>>();
    dag_global_kernel<<<GRID, NTHR>>>(roots, W1, b1, W2, b2, idx, typ, out);
}

// round 13
// speedup vs baseline: 1.4165x; 1.0017x over previous
#include <cuda_runtime.h>
#include <math.h>

#define BB 256
#define NN 2048
#define RR 64
#define DD 64
#define TT 8
#define HH 128
#define KD 128

#define GRID    296           // 2 CTAs on every SM (148 x 2), all co-resident
#define NTHR    256
#define MCH     32            // nodes per chunk
#define MS      (MCH + 4)     // smem row stride
#define LMAX    256
#define NGRP    (LMAX * TT)   // bucket key = t*LMAX + L

// packed f32x2 ops (sm_103a double-rate fp32 path; ptxas never auto-emits)
#define FMA_F32X2(d, a, b, c) \
    asm("fma.rn.f32x2 %0, %1, %2, %3;" : "=l"(d) : "l"(a), "l"(b), "l"(c))
#define PACK_F32X2(out, lo, hi) \
    asm("mov.b64 %0, {%1, %2};" : "=l"(out) : "f"(lo), "f"(hi))
#define UNPACK_F32X2(lo, hi, in) \
    asm("mov.b64 {%0, %1}, %2;" : "=f"(lo), "=f"(hi) : "l"(in))

// ---------------- global scratch (static: no allocation) ----------------
__device__ unsigned           g_arrive;
__device__ volatile unsigned  g_release;
__device__ int                g_cnt[NGRP];
__device__ int                g_cur[NGRP];             // scatter cursors
__device__ int                g_off[NGRP + 1];
__device__ int                g_ccum[TT * (LMAX + 1)]; // per-type chunk prefix over levels
__device__ int                g_tcur[TT];              // per-type team chunk cursor
__device__ int                g_maxl;
__device__ unsigned long long g_items[BB * (NN - RR)]; // (b<<33)|(n<<22)|(p0<<11)|p1
__device__ unsigned           g_flag[BB * NN];         // node-done flags

__global__ void reset_kernel()
{
    int gt = blockIdx.x * NTHR + threadIdx.x;
    for (int i = gt; i < BB * NN; i += GRID * NTHR) g_flag[i] = 0u;
    for (int i = gt; i < NGRP;   i += GRID * NTHR) g_cnt[i] = 0;
    if (gt < TT) g_tcur[gt] = 0;
    if (gt == 0) { g_arrive = 0; g_release = 0; g_maxl = 0; }
}

__device__ __forceinline__ void grid_barrier(int k)
{
    __syncthreads();
    if (threadIdx.x == 0) {
        __threadfence();   // release side
        unsigned old = atomicAdd(&g_arrive, 1u);
        if (old == (unsigned)(k * GRID - 1)) {
            g_release = (unsigned)k;
        } else {
            while (g_release < (unsigned)k) { }
        }
        __threadfence();   // acquire side
    }
    __syncthreads();
}

// STRONG scoped flag ops — the canonical PTX release/acquire message pair.
__device__ __forceinline__ unsigned ld_acq_u32(const unsigned* p)
{
    unsigned v;
    asm volatile("ld.acquire.gpu.global.u32 %0, [%1];"
                 : "=r"(v) : "l"(p) : "memory");
    return v;
}
__device__ __forceinline__ void st_rel_u32(unsigned* p, unsigned v)
{
    asm volatile("st.release.gpu.global.u32 [%0], %1;"
                 :: "l"(p), "r"(v) : "memory");
}

__global__ __launch_bounds__(NTHR, 2)
void dag_global_kernel(const float* __restrict__ roots,
                       const float* __restrict__ W1,
                       const float* __restrict__ b1,
                       const float* __restrict__ W2,
                       const float* __restrict__ b2,
                       const int*   __restrict__ g_idx,
                       const int*   __restrict__ g_typ,
                       float*       __restrict__ buf)
{
    const int b    = blockIdx.x;
    const int tid  = threadIdx.x;
    const int lane = tid & 31;
    const int wid  = tid >> 5;

    __shared__ __align__(16) float s_xs[KD * MS];
    __shared__ __align__(16) float s_hs[HH * MS];
    __shared__ unsigned long long s_it[MCH];     // chunk items (smem copy)
    __shared__ int s_ccum[LMAX + 1];
    __shared__ int s_k;

    unsigned short* s_lvl  = (unsigned short*)s_xs;   // prep aliases
    unsigned short* s_pidx = (unsigned short*)s_hs;

    // ---------------- prep (graphs 0..BB-1 handled by CTAs 0..BB-1) ----------
    if (b < BB) {
        const int* idxb = g_idx + (size_t)b * (NN * 2);
        const float* rs = roots + (size_t)b * (RR * DD);
        float*       bb = buf   + (size_t)b * (NN * DD);
        for (int i = tid; i < RR * DD; i += NTHR) bb[i] = rs[i];
        for (int k = tid; k < NN * 2; k += NTHR)
            s_pidx[k] = (unsigned short)idxb[k];
        for (int n = tid; n < RR; n += NTHR)
            g_flag[b * NN + n] = 1u;
        __syncthreads();

        if (tid == 0) {
            for (int n = 0; n < RR; ++n) s_lvl[n] = 0;
            int mx = 0;
            for (int n = RR; n < NN; ++n) {
                int l0 = s_lvl[s_pidx[n * 2 + 0]];
                int l1 = s_lvl[s_pidx[n * 2 + 1]];
                int l  = 1 + (l0 > l1 ? l0 : l1);
                s_lvl[n] = (unsigned short)l;
                if (l > mx) mx = l;
            }
            atomicMax(&g_maxl, mx);
        }
        __syncthreads();

        const int* typb = g_typ + (size_t)b * NN;
        for (int n = RR + tid; n < NN; n += NTHR)
            atomicAdd(&g_cnt[typb[n] * LMAX + (int)s_lvl[n]], 1);
    }

    grid_barrier(1);

    // CTA0: per-type prefix sums (8 threads, one per type)
    if (b == 0) {
        __shared__ int s_ttot[TT];
        if (tid < TT) {
            int tot = 0;
            for (int L = 0; L < LMAX; ++L) tot += g_cnt[tid * LMAX + L];
            s_ttot[tid] = tot;
        }
        __syncthreads();
        if (tid < TT) {
            int base = 0;
            for (int t = 0; t < tid; ++t) base += s_ttot[t];
            int acc = base;
            for (int L = 0; L < LMAX; ++L) {
                g_off[tid * LMAX + L] = acc;
                g_cur[tid * LMAX + L] = acc;
                acc += g_cnt[tid * LMAX + L];
            }
            if (tid == TT - 1) g_off[NGRP] = acc;
            int cacc = 0;
            g_ccum[tid * (LMAX + 1)] = 0;
            for (int L = 1; L <= LMAX; ++L) {
                cacc += (g_cnt[tid * LMAX + L] + MCH - 1) / MCH;
                g_ccum[tid * (LMAX + 1) + L] = cacc;
            }
        }
    }
    grid_barrier(2);

    // scatter items (64-bit packed with parent indices)
    if (b < BB) {
        const int* typb = g_typ + (size_t)b * NN;
        for (int n = RR + tid; n < NN; n += NTHR) {
            int key = typb[n] * LMAX + (int)s_lvl[n];
            int pos = atomicAdd(&g_cur[key], 1);
            unsigned long long p0 = s_pidx[n * 2 + 0];
            unsigned long long p1 = s_pidx[n * 2 + 1];
            g_items[pos] = ((unsigned long long)b << 33)
                         | ((unsigned long long)n << 22) | (p0 << 11) | p1;
        }
    }
    grid_barrier(3);

    // ---------------- dataflow main loop ----------------
    const int tmy = b % TT;              // uniform teams of 37 CTAs
    const int Lmx = *(volatile int*)&g_maxl;

    for (int i = tid; i <= LMAX; i += NTHR) s_ccum[i] = g_ccum[tmy * (LMAX + 1) + i];
    __syncthreads();
    const int total = s_ccum[Lmx];

    const float* w1t = W1 + (size_t)tmy * (KD * HH);
    const float* w2t = W2 + (size_t)tmy * (HH * DD);
    const float  bv1 = __ldg(b1 + tmy * HH + (tid & 127));
    const float  bv2 = __ldg(b2 + tmy * DD + (tid & 63));

    const int j128 = tid & 127, mh = tid >> 7;
    const int d64  = tid & 63,  mq = tid >> 6;

    while (true) {
        if (tid == 0) s_k = atomicAdd(&g_tcur[tmy], 1);
        __syncthreads();
        const int k = s_k;
        if (k >= total) break;

        // locate (level, chunk-in-level)
        int loL = 1, hiL = Lmx;
        while (loL < hiL) { int mid = (loL + hiL) >> 1;
                            if (s_ccum[mid] > k) hiL = mid; else loL = mid + 1; }
        const int L    = loL;
        const int cidx = k - s_ccum[L - 1];
        const int base = g_off[tmy * LMAX + L];
        const int cnt  = g_off[tmy * LMAX + L + 1] - base;
        const int goff = base + cidx * MCH;
        const int Mc   = min(MCH, cnt - cidx * MCH);

        // stage items into smem (consumed after the gather sync)
        if (tid < Mc) s_it[tid] = g_items[goff + tid];

        // ---- two-phase poll: batch-issue all acquire loads (MLP=8), then
        //      spin only on the (rare) zeros ----
        unsigned long long itv[4];
        const unsigned* fp0[4];
        const unsigned* fp1[4];
        unsigned fa[4], fb[4];
        #pragma unroll
        for (int r = 0; r < 4; ++r) {
            int m = wid + r * 8;
            itv[r] = 0; fa[r] = 1u; fb[r] = 1u; fp0[r] = 0; fp1[r] = 0;
            if (m < Mc) {
                itv[r] = g_items[goff + m];
                unsigned gb = (unsigned)(itv[r] >> 33);
                unsigned p0 = (unsigned)(itv[r] >> 11) & 2047u;
                unsigned p1 = (unsigned)itv[r] & 2047u;
                fp0[r] = &g_flag[gb * NN + p0];
                fp1[r] = &g_flag[gb * NN + p1];
                fa[r] = ld_acq_u32(fp0[r]);
                fb[r] = ld_acq_u32(fp1[r]);
            }
        }
        #pragma unroll
        for (int r = 0; r < 4; ++r) {
            if (fa[r] == 0u) { while (ld_acq_u32(fp0[r]) == 0u) { } }
            if (fb[r] == 0u) { while (ld_acq_u32(fp1[r]) == 0u) { } }
        }

        // ---- gather (ordered after acquire loads in program order) ----
        #pragma unroll
        for (int r = 0; r < 4; ++r) {
            int m = wid + r * 8;
            if (m < Mc) {
                unsigned gb = (unsigned)(itv[r] >> 33);
                unsigned p0 = (unsigned)(itv[r] >> 11) & 2047u;
                unsigned p1 = (unsigned)itv[r] & 2047u;
                const float* r0 = buf + ((size_t)gb * NN + p0) * DD;
                const float* r1 = buf + ((size_t)gb * NN + p1) * DD;
                s_xs[(lane      ) * MS + m] = __ldcg(r0 + lane);
                s_xs[(lane + 32 ) * MS + m] = __ldcg(r0 + lane + 32);
                s_xs[(lane + 64 ) * MS + m] = __ldcg(r1 + lane);
                s_xs[(lane + 96 ) * MS + m] = __ldcg(r1 + lane + 32);
            }
        }
        __syncthreads();

        // ---- GEMM1 + bias + GELU: pipelined weights + packed f32x2 FMA ----
        {
            const float* wp = w1t + j128;
            const float* xp = s_xs + mh * 16;
            unsigned long long acc[8];
            #pragma unroll
            for (int q = 0; q < 8; ++q) acc[q] = 0ull;   // (0.0f, 0.0f)
            float wc0 = __ldg(wp + 0 * HH);
            float wc1 = __ldg(wp + 1 * HH);
            float wc2 = __ldg(wp + 2 * HH);
            float wc3 = __ldg(wp + 3 * HH);
            #pragma unroll 1
            for (int i = 0; i < KD; i += 4) {
                const int ip = (i + 4) & (KD - 1);   // wrap: harmless reload of block 0
                float wn0 = __ldg(wp + (ip + 0) * HH);
                float wn1 = __ldg(wp + (ip + 1) * HH);
                float wn2 = __ldg(wp + (ip + 2) * HH);
                float wn3 = __ldg(wp + (ip + 3) * HH);
                #pragma unroll
                for (int u = 0; u < 4; ++u) {
                    float wv = (u == 0) ? wc0 : (u == 1) ? wc1 : (u == 2) ? wc2 : wc3;
                    unsigned long long wv2;
                    PACK_F32X2(wv2, wv, wv);
                    const float* xr = xp + (i + u) * MS;
                    ulonglong2 x01 = *(const ulonglong2*)(xr     );
                    ulonglong2 x23 = *(const ulonglong2*)(xr + 4 );
                    ulonglong2 x45 = *(const ulonglong2*)(xr + 8 );
                    ulonglong2 x67 = *(const ulonglong2*)(xr + 12);
                    FMA_F32X2(acc[0], x01.x, wv2, acc[0]);
                    FMA_F32X2(acc[1], x01.y, wv2, acc[1]);
                    FMA_F32X2(acc[2], x23.x, wv2, acc[2]);
                    FMA_F32X2(acc[3], x23.y, wv2, acc[3]);
                    FMA_F32X2(acc[4], x45.x, wv2, acc[4]);
                    FMA_F32X2(acc[5], x45.y, wv2, acc[5]);
                    FMA_F32X2(acc[6], x67.x, wv2, acc[6]);
                    FMA_F32X2(acc[7], x67.y, wv2, acc[7]);
                }
                wc0 = wn0; wc1 = wn1; wc2 = wn2; wc3 = wn3;
            }
            float a[16];
            #pragma unroll
            for (int q = 0; q < 8; ++q)
                UNPACK_F32X2(a[2 * q], a[2 * q + 1], acc[q]);
            #pragma unroll
            for (int q = 0; q < 16; ++q) {
                float v = a[q] + bv1;
                a[q] = 0.5f * v * (1.0f + erff(v * 0.70710678118654752440f));
            }
            float* hp = s_hs + j128 * MS + mh * 16;
            *(float4*)(hp     ) = make_float4(a[0],  a[1],  a[2],  a[3]);
            *(float4*)(hp + 4 ) = make_float4(a[4],  a[5],  a[6],  a[7]);
            *(float4*)(hp + 8 ) = make_float4(a[8],  a[9],  a[10], a[11]);
            *(float4*)(hp + 12) = make_float4(a[12], a[13], a[14], a[15]);
        }
        __syncthreads();

        // ---- GEMM2 + bias + store: pipelined weights + packed f32x2 FMA ----
        {
            const float* wp = w2t + d64;
            const float* hp = s_hs + mq * 8;
            unsigned long long acc[4];
            #pragma unroll
            for (int q = 0; q < 4; ++q) acc[q] = 0ull;
            float wc0 = __ldg(wp + 0 * DD);
            float wc1 = __ldg(wp + 1 * DD);
            float wc2 = __ldg(wp + 2 * DD);
            float wc3 = __ldg(wp + 3 * DD);
            #pragma unroll 1
            for (int j = 0; j < HH; j += 4) {
                const int jp = (j + 4) & (HH - 1);
                float wn0 = __ldg(wp + (jp + 0) * DD);
                float wn1 = __ldg(wp + (jp + 1) * DD);
                float wn2 = __ldg(wp + (jp + 2) * DD);
                float wn3 = __ldg(wp + (jp + 3) * DD);
                #pragma unroll
                for (int u = 0; u < 4; ++u) {
                    float wv = (u == 0) ? wc0 : (u == 1) ? wc1 : (u == 2) ? wc2 : wc3;
                    unsigned long long wv2;
                    PACK_F32X2(wv2, wv, wv);
                    const float* hr = hp + (j + u) * MS;
                    ulonglong2 h01 = *(const ulonglong2*)(hr    );
                    ulonglong2 h23 = *(const ulonglong2*)(hr + 4);
                    FMA_F32X2(acc[0], h01.x, wv2, acc[0]);
                    FMA_F32X2(acc[1], h01.y, wv2, acc[1]);
                    FMA_F32X2(acc[2], h23.x, wv2, acc[2]);
                    FMA_F32X2(acc[3], h23.y, wv2, acc[3]);
                }
                wc0 = wn0; wc1 = wn1; wc2 = wn2; wc3 = wn3;
            }
            float o[8];
            #pragma unroll
            for (int q = 0; q < 4; ++q)
                UNPACK_F32X2(o[2 * q], o[2 * q + 1], acc[q]);
            #pragma unroll
            for (int q = 0; q < 8; ++q) {
                int m = mq * 8 + q;
                if (m < Mc) {
                    unsigned long long it = s_it[m];             // broadcast LDS
                    unsigned gb = (unsigned)(it >> 33);
                    unsigned gn = (unsigned)(it >> 22) & 2047u;
                    buf[((size_t)gb * NN + gn) * DD + d64] = o[q] + bv2;
                }
            }
        }

        // ---- publish: bar (intra-CTA HB) -> release-store (gpu-scope) ----
        __syncthreads();
        if (tid < Mc) {
            unsigned long long it = s_it[tid];
            unsigned gb = (unsigned)(it >> 33);
            unsigned gn = (unsigned)(it >> 22) & 2047u;
            st_rel_u32(&g_flag[gb * NN + gn], 1u);
        }
    }
}

extern "C" void kernel_launch(void* const* d_in, const int* in_sizes, int n_in,
                              void* d_out, int out_size)
{
    const float* roots = (const float*)d_in[0];
    const float* W1    = (const float*)d_in[1];
    const float* b1    = (const float*)d_in[2];
    const float* W2    = (const float*)d_in[3];
    const float* b2    = (const float*)d_in[4];
    const int*   idx   = (const int*)  d_in[5];
    const int*   typ   = (const int*)  d_in[6];
    float*       out   = (float*)d_out;

    reset_kernel<<<GRID, NTHR>>>();
    dag_global_kernel<<<GRID, NTHR>>>(roots, W1, b1, W2, b2, idx, typ, out);
}

// round 14
// speedup vs baseline: 1.6272x; 1.1487x over previous
#include <cuda_runtime.h>
#include <math.h>

#define BB 256
#define NN 2048
#define RR 64
#define DD 64
#define TT 8
#define HH 128
#define KD 128

#define GRID    444           // 3 CTAs on every SM (148 x 3), all co-resident
#define NTHR    256
#define MCH     32            // nodes per chunk
#define MS      (MCH + 4)     // smem row stride
#define LMAX    256
#define NGRP    (LMAX * TT)   // bucket key = t*LMAX + L

// packed f32x2 ops (sm_103a double-rate fp32 path; ptxas never auto-emits)
#define FMA_F32X2(d, a, b, c) \
    asm("fma.rn.f32x2 %0, %1, %2, %3;" : "=l"(d) : "l"(a), "l"(b), "l"(c))
#define PACK_F32X2(out, lo, hi) \
    asm("mov.b64 %0, {%1, %2};" : "=l"(out) : "f"(lo), "f"(hi))
#define UNPACK_F32X2(lo, hi, in) \
    asm("mov.b64 {%0, %1}, %2;" : "=f"(lo), "=f"(hi) : "l"(in))

// ---------------- global scratch (static: no allocation) ----------------
__device__ unsigned           g_arrive;
__device__ volatile unsigned  g_release;
__device__ int                g_cnt[NGRP];
__device__ int                g_cur[NGRP];             // scatter cursors
__device__ int                g_off[NGRP + 1];
__device__ int                g_ccum[TT * (LMAX + 1)]; // per-type chunk prefix over levels
__device__ int                g_tcur[TT];              // per-type team chunk cursor
__device__ int                g_maxl;
__device__ unsigned long long g_items[BB * (NN - RR)]; // (b<<33)|(n<<22)|(p0<<11)|p1
__device__ unsigned           g_flag[BB * NN];         // node-done flags

__global__ void reset_kernel()
{
    int gt = blockIdx.x * NTHR + threadIdx.x;
    for (int i = gt; i < BB * NN; i += GRID * NTHR) g_flag[i] = 0u;
    for (int i = gt; i < NGRP;   i += GRID * NTHR) g_cnt[i] = 0;
    if (gt < TT) g_tcur[gt] = 0;
    if (gt == 0) { g_arrive = 0; g_release = 0; g_maxl = 0; }
}

__device__ __forceinline__ void grid_barrier(int k)
{
    __syncthreads();
    if (threadIdx.x == 0) {
        __threadfence();   // release side
        unsigned old = atomicAdd(&g_arrive, 1u);
        if (old == (unsigned)(k * GRID - 1)) {
            g_release = (unsigned)k;
        } else {
            while (g_release < (unsigned)k) { }
        }
        __threadfence();   // acquire side
    }
    __syncthreads();
}

// STRONG scoped flag ops — the canonical PTX release/acquire message pair.
__device__ __forceinline__ unsigned ld_acq_u32(const unsigned* p)
{
    unsigned v;
    asm volatile("ld.acquire.gpu.global.u32 %0, [%1];"
                 : "=r"(v) : "l"(p) : "memory");
    return v;
}
__device__ __forceinline__ void st_rel_u32(unsigned* p, unsigned v)
{
    asm volatile("st.release.gpu.global.u32 [%0], %1;"
                 :: "l"(p), "r"(v) : "memory");
}

__global__ __launch_bounds__(NTHR, 3)
void dag_global_kernel(const float* __restrict__ roots,
                       const float* __restrict__ W1,
                       const float* __restrict__ b1,
                       const float* __restrict__ W2,
                       const float* __restrict__ b2,
                       const int*   __restrict__ g_idx,
                       const int*   __restrict__ g_typ,
                       float*       __restrict__ buf)
{
    const int b    = blockIdx.x;
    const int tid  = threadIdx.x;
    const int lane = tid & 31;
    const int wid  = tid >> 5;

    __shared__ __align__(16) float s_xs[KD * MS];
    __shared__ __align__(16) float s_hs[HH * MS];
    __shared__ unsigned long long s_it[MCH];     // chunk items (smem copy)
    __shared__ int s_ccum[LMAX + 1];
    __shared__ int s_k;

    unsigned short* s_lvl  = (unsigned short*)s_xs;   // prep aliases
    unsigned short* s_pidx = (unsigned short*)s_hs;

    // ---------------- prep (graphs 0..BB-1 handled by CTAs 0..BB-1) ----------
    if (b < BB) {
        const int* idxb = g_idx + (size_t)b * (NN * 2);
        const float* rs = roots + (size_t)b * (RR * DD);
        float*       bb = buf   + (size_t)b * (NN * DD);
        for (int i = tid; i < RR * DD; i += NTHR) bb[i] = rs[i];
        for (int k = tid; k < NN * 2; k += NTHR)
            s_pidx[k] = (unsigned short)idxb[k];
        for (int n = tid; n < RR; n += NTHR)
            g_flag[b * NN + n] = 1u;
        __syncthreads();

        if (tid == 0) {
            for (int n = 0; n < RR; ++n) s_lvl[n] = 0;
            int mx = 0;
            for (int n = RR; n < NN; ++n) {
                int l0 = s_lvl[s_pidx[n * 2 + 0]];
                int l1 = s_lvl[s_pidx[n * 2 + 1]];
                int l  = 1 + (l0 > l1 ? l0 : l1);
                s_lvl[n] = (unsigned short)l;
                if (l > mx) mx = l;
            }
            atomicMax(&g_maxl, mx);
        }
        __syncthreads();

        const int* typb = g_typ + (size_t)b * NN;
        for (int n = RR + tid; n < NN; n += NTHR)
            atomicAdd(&g_cnt[typb[n] * LMAX + (int)s_lvl[n]], 1);
    }

    grid_barrier(1);

    // CTA0: per-type prefix sums (8 threads, one per type)
    if (b == 0) {
        __shared__ int s_ttot[TT];
        if (tid < TT) {
            int tot = 0;
            for (int L = 0; L < LMAX; ++L) tot += g_cnt[tid * LMAX + L];
            s_ttot[tid] = tot;
        }
        __syncthreads();
        if (tid < TT) {
            int base = 0;
            for (int t = 0; t < tid; ++t) base += s_ttot[t];
            int acc = base;
            for (int L = 0; L < LMAX; ++L) {
                g_off[tid * LMAX + L] = acc;
                g_cur[tid * LMAX + L] = acc;
                acc += g_cnt[tid * LMAX + L];
            }
            if (tid == TT - 1) g_off[NGRP] = acc;
            int cacc = 0;
            g_ccum[tid * (LMAX + 1)] = 0;
            for (int L = 1; L <= LMAX; ++L) {
                cacc += (g_cnt[tid * LMAX + L] + MCH - 1) / MCH;
                g_ccum[tid * (LMAX + 1) + L] = cacc;
            }
        }
    }
    grid_barrier(2);

    // scatter items (64-bit packed with parent indices)
    if (b < BB) {
        const int* typb = g_typ + (size_t)b * NN;
        for (int n = RR + tid; n < NN; n += NTHR) {
            int key = typb[n] * LMAX + (int)s_lvl[n];
            int pos = atomicAdd(&g_cur[key], 1);
            unsigned long long p0 = s_pidx[n * 2 + 0];
            unsigned long long p1 = s_pidx[n * 2 + 1];
            g_items[pos] = ((unsigned long long)b << 33)
                         | ((unsigned long long)n << 22) | (p0 << 11) | p1;
        }
    }
    grid_barrier(3);

    // ---------------- dataflow main loop ----------------
    const int tmy = b % TT;              // teams of 55-56 CTAs
    const int Lmx = *(volatile int*)&g_maxl;

    for (int i = tid; i <= LMAX; i += NTHR) s_ccum[i] = g_ccum[tmy * (LMAX + 1) + i];
    __syncthreads();
    const int total = s_ccum[Lmx];

    const float* w1t = W1 + (size_t)tmy * (KD * HH);
    const float* w2t = W2 + (size_t)tmy * (HH * DD);
    const float  bv1 = __ldg(b1 + tmy * HH + (tid & 127));
    const float  bv2 = __ldg(b2 + tmy * DD + (tid & 63));

    const int j128 = tid & 127, mh = tid >> 7;
    const int d64  = tid & 63,  mq = tid >> 6;

    while (true) {
        if (tid == 0) s_k = atomicAdd(&g_tcur[tmy], 1);
        __syncthreads();
        const int k = s_k;
        if (k >= total) break;

        // locate (level, chunk-in-level)
        int loL = 1, hiL = Lmx;
        while (loL < hiL) { int mid = (loL + hiL) >> 1;
                            if (s_ccum[mid] > k) hiL = mid; else loL = mid + 1; }
        const int L    = loL;
        const int cidx = k - s_ccum[L - 1];
        const int base = g_off[tmy * LMAX + L];
        const int cnt  = g_off[tmy * LMAX + L + 1] - base;
        const int goff = base + cidx * MCH;
        const int Mc   = min(MCH, cnt - cidx * MCH);

        // stage items into smem (consumed after the gather sync)
        if (tid < Mc) s_it[tid] = g_items[goff + tid];

        // ---- two-phase poll: batch acquire loads (MLP=8), spin on rare misses.
        //      Compact form: miss bitmask + address recompute (register diet).
        unsigned long long itv[4];
        unsigned miss = 0u;
        #pragma unroll
        for (int r = 0; r < 4; ++r) {
            int m = wid + r * 8;
            itv[r] = 0;
            if (m < Mc) {
                itv[r] = g_items[goff + m];
                unsigned gb = (unsigned)(itv[r] >> 33);
                unsigned p0 = (unsigned)(itv[r] >> 11) & 2047u;
                unsigned p1 = (unsigned)itv[r] & 2047u;
                if (ld_acq_u32(&g_flag[gb * NN + p0]) == 0u) miss |= 1u << (2 * r);
                if (ld_acq_u32(&g_flag[gb * NN + p1]) == 0u) miss |= 1u << (2 * r + 1);
            }
        }
        if (miss) {
            #pragma unroll
            for (int r = 0; r < 4; ++r) {
                unsigned gb = (unsigned)(itv[r] >> 33);
                unsigned p0 = (unsigned)(itv[r] >> 11) & 2047u;
                unsigned p1 = (unsigned)itv[r] & 2047u;
                if (miss & (1u << (2 * r)))
                    while (ld_acq_u32(&g_flag[gb * NN + p0]) == 0u) { }
                if (miss & (1u << (2 * r + 1)))
                    while (ld_acq_u32(&g_flag[gb * NN + p1]) == 0u) { }
            }
        }

        // ---- gather (ordered after acquire loads in program order) ----
        #pragma unroll
        for (int r = 0; r < 4; ++r) {
            int m = wid + r * 8;
            if (m < Mc) {
                unsigned gb = (unsigned)(itv[r] >> 33);
                unsigned p0 = (unsigned)(itv[r] >> 11) & 2047u;
                unsigned p1 = (unsigned)itv[r] & 2047u;
                const float* r0 = buf + ((size_t)gb * NN + p0) * DD;
                const float* r1 = buf + ((size_t)gb * NN + p1) * DD;
                s_xs[(lane      ) * MS + m] = __ldcg(r0 + lane);
                s_xs[(lane + 32 ) * MS + m] = __ldcg(r0 + lane + 32);
                s_xs[(lane + 64 ) * MS + m] = __ldcg(r1 + lane);
                s_xs[(lane + 96 ) * MS + m] = __ldcg(r1 + lane + 32);
            }
        }
        __syncthreads();

        // ---- GEMM1 + bias + GELU: pipelined weights + packed f32x2 FMA ----
        {
            const float* wp = w1t + j128;
            const float* xp = s_xs + mh * 16;
            unsigned long long acc[8];
            #pragma unroll
            for (int q = 0; q < 8; ++q) acc[q] = 0ull;   // (0.0f, 0.0f)
            float wc0 = __ldg(wp + 0 * HH);
            float wc1 = __ldg(wp + 1 * HH);
            float wc2 = __ldg(wp + 2 * HH);
            float wc3 = __ldg(wp + 3 * HH);
            #pragma unroll 1
            for (int i = 0; i < KD; i += 4) {
                const int ip = (i + 4) & (KD - 1);   // wrap: harmless reload of block 0
                float wn0 = __ldg(wp + (ip + 0) * HH);
                float wn1 = __ldg(wp + (ip + 1) * HH);
                float wn2 = __ldg(wp + (ip + 2) * HH);
                float wn3 = __ldg(wp + (ip + 3) * HH);
                #pragma unroll
                for (int u = 0; u < 4; ++u) {
                    float wv = (u == 0) ? wc0 : (u == 1) ? wc1 : (u == 2) ? wc2 : wc3;
                    unsigned long long wv2;
                    PACK_F32X2(wv2, wv, wv);
                    const float* xr = xp + (i + u) * MS;
                    ulonglong2 x01 = *(const ulonglong2*)(xr     );
                    ulonglong2 x23 = *(const ulonglong2*)(xr + 4 );
                    ulonglong2 x45 = *(const ulonglong2*)(xr + 8 );
                    ulonglong2 x67 = *(const ulonglong2*)(xr + 12);
                    FMA_F32X2(acc[0], x01.x, wv2, acc[0]);
                    FMA_F32X2(acc[1], x01.y, wv2, acc[1]);
                    FMA_F32X2(acc[2], x23.x, wv2, acc[2]);
                    FMA_F32X2(acc[3], x23.y, wv2, acc[3]);
                    FMA_F32X2(acc[4], x45.x, wv2, acc[4]);
                    FMA_F32X2(acc[5], x45.y, wv2, acc[5]);
                    FMA_F32X2(acc[6], x67.x, wv2, acc[6]);
                    FMA_F32X2(acc[7], x67.y, wv2, acc[7]);
                }
                wc0 = wn0; wc1 = wn1; wc2 = wn2; wc3 = wn3;
            }
            float a[16];
            #pragma unroll
            for (int q = 0; q < 8; ++q)
                UNPACK_F32X2(a[2 * q], a[2 * q + 1], acc[q]);
            #pragma unroll
            for (int q = 0; q < 16; ++q) {
                float v = a[q] + bv1;
                a[q] = 0.5f * v * (1.0f + erff(v * 0.70710678118654752440f));
            }
            float* hp = s_hs + j128 * MS + mh * 16;
            *(float4*)(hp     ) = make_float4(a[0],  a[1],  a[2],  a[3]);
            *(float4*)(hp + 4 ) = make_float4(a[4],  a[5],  a[6],  a[7]);
            *(float4*)(hp + 8 ) = make_float4(a[8],  a[9],  a[10], a[11]);
            *(float4*)(hp + 12) = make_float4(a[12], a[13], a[14], a[15]);
        }
        __syncthreads();

        // ---- GEMM2 + bias + store: pipelined weights + packed f32x2 FMA ----
        {
            const float* wp = w2t + d64;
            const float* hp = s_hs + mq * 8;
            unsigned long long acc[4];
            #pragma unroll
            for (int q = 0; q < 4; ++q) acc[q] = 0ull;
            float wc0 = __ldg(wp + 0 * DD);
            float wc1 = __ldg(wp + 1 * DD);
            float wc2 = __ldg(wp + 2 * DD);
            float wc3 = __ldg(wp + 3 * DD);
            #pragma unroll 1
            for (int j = 0; j < HH; j += 4) {
                const int jp = (j + 4) & (HH - 1);
                float wn0 = __ldg(wp + (jp + 0) * DD);
                float wn1 = __ldg(wp + (jp + 1) * DD);
                float wn2 = __ldg(wp + (jp + 2) * DD);
                float wn3 = __ldg(wp + (jp + 3) * DD);
                #pragma unroll
                for (int u = 0; u < 4; ++u) {
                    float wv = (u == 0) ? wc0 : (u == 1) ? wc1 : (u == 2) ? wc2 : wc3;
                    unsigned long long wv2;
                    PACK_F32X2(wv2, wv, wv);
                    const float* hr = hp + (j + u) * MS;
                    ulonglong2 h01 = *(const ulonglong2*)(hr    );
                    ulonglong2 h23 = *(const ulonglong2*)(hr + 4);
                    FMA_F32X2(acc[0], h01.x, wv2, acc[0]);
                    FMA_F32X2(acc[1], h01.y, wv2, acc[1]);
                    FMA_F32X2(acc[2], h23.x, wv2, acc[2]);
                    FMA_F32X2(acc[3], h23.y, wv2, acc[3]);
                }
                wc0 = wn0; wc1 = wn1; wc2 = wn2; wc3 = wn3;
            }
            float o[8];
            #pragma unroll
            for (int q = 0; q < 4; ++q)
                UNPACK_F32X2(o[2 * q], o[2 * q + 1], acc[q]);
            #pragma unroll
            for (int q = 0; q < 8; ++q) {
                int m = mq * 8 + q;
                if (m < Mc) {
                    unsigned long long it = s_it[m];             // broadcast LDS
                    unsigned gb = (unsigned)(it >> 33);
                    unsigned gn = (unsigned)(it >> 22) & 2047u;
                    buf[((size_t)gb * NN + gn) * DD + d64] = o[q] + bv2;
                }
            }
        }

        // ---- publish: bar (intra-CTA HB) -> release-store (gpu-scope) ----
        __syncthreads();
        if (tid < Mc) {
            unsigned long long it = s_it[tid];
            unsigned gb = (unsigned)(it >> 33);
            unsigned gn = (unsigned)(it >> 22) & 2047u;
            st_rel_u32(&g_flag[gb * NN + gn], 1u);
        }
    }
}

extern "C" void kernel_launch(void* const* d_in, const int* in_sizes, int n_in,
                              void* d_out, int out_size)
{
    const float* roots = (const float*)d_in[0];
    const float* W1    = (const float*)d_in[1];
    const float* b1    = (const float*)d_in[2];
    const float* W2    = (const float*)d_in[3];
    const float* b2    = (const float*)d_in[4];
    const int*   idx   = (const int*)  d_in[5];
    const int*   typ   = (const int*)  d_in[6];
    float*       out   = (float*)d_out;

    reset_kernel<<<GRID, NTHR>>>();
    dag_global_kernel<<<GRID, NTHR>>>(roots, W1, b1, W2, b2, idx, typ, out);
}